// round 11
// baseline (speedup 1.0000x reference)
#include <cuda_runtime.h>
#include <cstddef>

// BiLSTM tagger: B=128, T=512, V=50000, E=256, H=512, TAGS=64
#define Mn 65536
#define Tn 512
#define Hn 512

typedef unsigned long long ull;

// ---------------- static device scratch (no allocations allowed) ----------
__device__ float g_gx[2ULL * Mn * 2048];        // gx for fwd+bwd of current layer
__device__ float g_out1[(size_t)Mn * 1024];     // layer1 output [b][t][1024]
__device__ float g_out2[(size_t)Mn * 1024];     // layer2 output
__device__ float g_h[2][2][Hn * 128];           // [dir][parity][unit*128+batch]
__device__ unsigned g_ctr[4];                   // grid-barrier counters

// ---------------- f32x2 helpers (FFMA2 is PTX-only) ------------------------
__device__ __forceinline__ ull dup2(float v) {
    ull r; asm("mov.b64 %0, {%1, %1};" : "=l"(r) : "f"(v)); return r;
}
__device__ __forceinline__ ull pack2(float a, float b) {
    ull r; asm("mov.b64 %0, {%1, %2};" : "=l"(r) : "f"(a), "f"(b)); return r;
}
__device__ __forceinline__ ull ffma2(ull a, ull b, ull c) {
    ull d; asm("fma.rn.f32x2 %0, %1, %2, %3;" : "=l"(d) : "l"(a), "l"(b), "l"(c));
    return d;
}
__device__ __forceinline__ float fsig(float x) { return 1.0f / (1.0f + __expf(-x)); }

__global__ void zero_ctr() { if (threadIdx.x < 4) g_ctr[threadIdx.x] = 0u; }

// ===========================================================================
// GEMM: C[M,N] = A[M,K] @ W[N,K]^T + bias[N]   (validated in round 7)
// ===========================================================================
template <int BN, bool GATHER>
__global__ void __launch_bounds__(256) gemm_k(
    const float* __restrict__ A, const int* __restrict__ xidx,
    const float* __restrict__ emb, const float* __restrict__ W,
    const float* __restrict__ bias, float* __restrict__ C,
    int N, int K)
{
    __shared__ float As[16 * 132];
    __shared__ float Bs[16 * (BN + 4)];
    constexpr int BP = BN + 4;
    constexpr int NJ = BN / 16;

    const int tid = threadIdx.x;
    const int m0 = blockIdx.x * 128, n0 = blockIdx.y * BN;
    const int rA = tid >> 2, kq = (tid & 3) * 4;

    const float *pa0, *pa1;
    if (GATHER) {
        pa0 = emb + (size_t)xidx[m0 + rA] * K + kq;
        pa1 = emb + (size_t)xidx[m0 + rA + 64] * K + kq;
    } else {
        pa0 = A + (size_t)(m0 + rA) * K + kq;
        pa1 = A + (size_t)(m0 + rA + 64) * K + kq;
    }
    const float* pb0 = W + (size_t)(n0 + rA) * K + kq;
    const float* pb1 = (BN == 128) ? (W + (size_t)(n0 + rA + 64) * K + kq) : pb0;

    const int tx = tid & 15, ty = tid >> 4;

    float acc[8][NJ];
#pragma unroll
    for (int j = 0; j < NJ; ++j) {
        float bv = bias[n0 + tx + 16 * j];
#pragma unroll
        for (int i = 0; i < 8; ++i) acc[i][j] = bv;
    }

    for (int kt = 0; kt < K; kt += 16) {
        float4 a0 = *(const float4*)(pa0 + kt);
        float4 a1 = *(const float4*)(pa1 + kt);
        float4 b0 = *(const float4*)(pb0 + kt);
        float4 b1 = make_float4(0.f, 0.f, 0.f, 0.f);
        if (BN == 128) b1 = *(const float4*)(pb1 + kt);

        As[(kq + 0) * 132 + rA] = a0.x;  As[(kq + 1) * 132 + rA] = a0.y;
        As[(kq + 2) * 132 + rA] = a0.z;  As[(kq + 3) * 132 + rA] = a0.w;
        As[(kq + 0) * 132 + rA + 64] = a1.x;  As[(kq + 1) * 132 + rA + 64] = a1.y;
        As[(kq + 2) * 132 + rA + 64] = a1.z;  As[(kq + 3) * 132 + rA + 64] = a1.w;
        Bs[(kq + 0) * BP + rA] = b0.x;   Bs[(kq + 1) * BP + rA] = b0.y;
        Bs[(kq + 2) * BP + rA] = b0.z;   Bs[(kq + 3) * BP + rA] = b0.w;
        if (BN == 128) {
            Bs[(kq + 0) * BP + rA + 64] = b1.x;  Bs[(kq + 1) * BP + rA + 64] = b1.y;
            Bs[(kq + 2) * BP + rA + 64] = b1.z;  Bs[(kq + 3) * BP + rA + 64] = b1.w;
        }
        __syncthreads();

#pragma unroll
        for (int k = 0; k < 16; ++k) {
            float av[8], bv[NJ];
#pragma unroll
            for (int i = 0; i < 8; ++i) av[i] = As[k * 132 + ty + 16 * i];
#pragma unroll
            for (int j = 0; j < NJ; ++j) bv[j] = Bs[k * BP + tx + 16 * j];
#pragma unroll
            for (int i = 0; i < 8; ++i)
#pragma unroll
                for (int j = 0; j < NJ; ++j) acc[i][j] += av[i] * bv[j];
        }
        __syncthreads();
    }

#pragma unroll
    for (int i = 0; i < 8; ++i) {
        float* cr = C + (size_t)(m0 + ty + 16 * i) * N + n0;
#pragma unroll
        for (int j = 0; j < NJ; ++j) cr[tx + 16 * j] = acc[i][j];
    }
}

// ===========================================================================
// Persistent bidirectional LSTM layer. Grid = 128 blocks x 256 threads,
// 1 block/SM (111 KB dyn smem) -> all co-resident on 148 SMs.
// Block owns 8 hidden units (32 gate rows x 128 batch, K=512).
// W_hh slice resident in smem (transposed, pitch 36); c in smem; h double-
// buffered in global [unit][batch], read with __ldcg (L1 stale across the
// software barrier inside one launch).
// Thread tile: ry=tid>>5 -> rows 4ry..4ry+3, bx=tid&31 -> 2 batch-pairs
// (2bx,2bx+1) and (2bx+64,2bx+65). W read is warp-broadcast LDS.128;
// h reads are conflict-free LDS.64.
// Barrier: per-dir counter; release = syncthreads + threadfence + atomicAdd,
// acquire = ld.acquire.gpu spin (tid 0) + syncthreads.
// Packed-seq semantics (validated round 7): step s valid iff s < len[b];
// bwd reads gx / writes out at t = len-1-s; dead (b,s) write 0 at t = s.
// ===========================================================================
__global__ void __launch_bounds__(256) rec_persist(
    const float* __restrict__ gxf, const float* __restrict__ gxb,
    const float* __restrict__ Wf, const float* __restrict__ Wb,
    const int* __restrict__ lengths, float* __restrict__ out, int ctrBase)
{
    extern __shared__ __align__(16) float sm[];
    float* Wst = sm;                      // 512*36 = 18432 floats
    float* Hs  = Wst + 512 * 36;          // 32*128 =  4096
    float* Gs  = Hs + 32 * 128;           // 32*128 =  4096
    float* cs  = Gs + 32 * 128;           // 8*128  =  1024
    int* slen  = (int*)(cs + 8 * 128);    // 128 ints

    const int tid = threadIdx.x;
    const int dir = blockIdx.x >> 6;
    const int u0  = (blockIdx.x & 63) * 8;
    const float* gx  = dir ? gxb : gxf;
    const float* Whh = dir ? Wb : Wf;
    unsigned* ctr = &g_ctr[ctrBase + dir];

    if (tid < 128) slen[tid] = lengths[tid];

    // ---- stage W_hh slice once: Wst[k][row], pitch 36 ----
#pragma unroll 4
    for (int rl = 0; rl < 32; ++rl) {
        const int grow = (rl >> 3) * Hn + u0 + (rl & 7);
        const float* wr = Whh + (size_t)grow * Hn;
        Wst[(size_t)tid * 36 + rl]         = wr[tid];
        Wst[(size_t)(tid + 256) * 36 + rl] = wr[tid + 256];
    }
    __syncthreads();

    const int ry = tid >> 5, bx = tid & 31;

    for (int s = 0; s < Tn; ++s) {
        // ---- acc init from gx (pre-barrier: touches only registers) ----
        ull acc[4][2];
#pragma unroll
        for (int i = 0; i < 4; ++i) {
            const int rl = 4 * ry + i;
            const int grow = (rl >> 3) * Hn + u0 + (rl & 7);
#pragma unroll
            for (int j = 0; j < 2; ++j) {
                float v[2];
#pragma unroll
                for (int e = 0; e < 2; ++e) {
                    const int b = 2 * bx + 64 * j + e;
                    const int L = slen[b];
                    const bool ok = (s < L);
                    const int t = ok ? (dir ? (L - 1 - s) : s) : 0;
                    v[e] = ok ? __ldg(gx + (size_t)(b * Tn + t) * 2048 + grow) : 0.0f;
                }
                acc[i][j] = pack2(v[0], v[1]);
            }
        }

        if (s > 0) {
            // ---- grid barrier: wait for all 64 blocks of this dir ----
            if (tid == 0) {
                const unsigned tgt = 64u * (unsigned)s;
                unsigned v;
                for (;;) {
                    asm volatile("ld.acquire.gpu.u32 %0, [%1];" : "=r"(v) : "l"(ctr));
                    if (v >= tgt) break;
                    __nanosleep(64);
                }
            }
            __syncthreads();

            // ---- recurrent gemv: += W_hh_slice @ h_prev, 16 chunks of 32 k ----
            const float* hp = &g_h[dir][(s - 1) & 1][0];
            for (int kc = 0; kc < 16; ++kc) {
                const float4* src = (const float4*)(hp + kc * 32 * 128);
                float4 hv[4];
#pragma unroll
                for (int i = 0; i < 4; ++i) hv[i] = __ldcg(src + tid + 256 * i);
                __syncthreads();           // previous chunk fully consumed
                float4* d4 = (float4*)Hs;
#pragma unroll
                for (int i = 0; i < 4; ++i) d4[tid + 256 * i] = hv[i];
                __syncthreads();

#pragma unroll 4
                for (int k = 0; k < 32; ++k) {
                    const float4 wv = *(const float4*)&Wst[(size_t)(kc * 32 + k) * 36 + 4 * ry];
                    const ull h0 = *(const ull*)&Hs[k * 128 + 2 * bx];
                    const ull h1 = *(const ull*)&Hs[k * 128 + 2 * bx + 64];
                    const ull w0 = dup2(wv.x), w1 = dup2(wv.y);
                    const ull w2 = dup2(wv.z), w3 = dup2(wv.w);
                    acc[0][0] = ffma2(w0, h0, acc[0][0]);
                    acc[0][1] = ffma2(w0, h1, acc[0][1]);
                    acc[1][0] = ffma2(w1, h0, acc[1][0]);
                    acc[1][1] = ffma2(w1, h1, acc[1][1]);
                    acc[2][0] = ffma2(w2, h0, acc[2][0]);
                    acc[2][1] = ffma2(w2, h1, acc[2][1]);
                    acc[3][0] = ffma2(w3, h0, acc[3][0]);
                    acc[3][1] = ffma2(w3, h1, acc[3][1]);
                }
            }
        }

        // ---- gates -> smem ----
#pragma unroll
        for (int i = 0; i < 4; ++i) {
            *(ull*)&Gs[(4 * ry + i) * 128 + 2 * bx]      = acc[i][0];
            *(ull*)&Gs[(4 * ry + i) * 128 + 2 * bx + 64] = acc[i][1];
        }
        __syncthreads();

        // ---- cell update: 8 units x 128 batch, 4 cells/thread ----
        float* hw = &g_h[dir][s & 1][0];
#pragma unroll
        for (int q = 0; q < 4; ++q) {
            const int cell = tid + 256 * q;
            const int u = cell >> 7, b = cell & 127;
            const int L = slen[b];
            float hval = 0.0f;
            int t = s;
            if (s < L) {
                const float gi = Gs[u * 128 + b];
                const float gf = Gs[(8 + u) * 128 + b];
                const float gg = Gs[(16 + u) * 128 + b];
                const float go = Gs[(24 + u) * 128 + b];
                const float cp = (s == 0) ? 0.0f : cs[cell];
                const float cn = fsig(gf) * cp + fsig(gi) * tanhf(gg);
                cs[cell] = cn;
                hval = fsig(go) * tanhf(cn);
                t = dir ? (L - 1 - s) : s;
            }
            hw[(u0 + u) * 128 + b] = hval;
            out[(size_t)(b * Tn + t) * 1024 + dir * Hn + u0 + u] = hval;
        }

        // ---- release: h for step s visible at gpu scope ----
        __syncthreads();
        if (tid == 0) {
            __threadfence();
            atomicAdd(ctr, 1u);
        }
    }
}

// ===========================================================================
extern "C" void kernel_launch(void* const* d_in, const int* in_sizes, int n_in,
                              void* d_out, int out_size)
{
    const int*   x       = (const int*)d_in[0];
    const int*   lengths = (const int*)d_in[1];
    const float* emb     = (const float*)d_in[2];
    const float* Wih_f1  = (const float*)d_in[3];
    const float* Whh_f1  = (const float*)d_in[4];
    const float* b_f1    = (const float*)d_in[5];
    const float* Wih_b1  = (const float*)d_in[6];
    const float* Whh_b1  = (const float*)d_in[7];
    const float* b_b1    = (const float*)d_in[8];
    const float* Wih_f2  = (const float*)d_in[9];
    const float* Whh_f2  = (const float*)d_in[10];
    const float* b_f2    = (const float*)d_in[11];
    const float* Wih_b2  = (const float*)d_in[12];
    const float* Whh_b2  = (const float*)d_in[13];
    const float* b_b2    = (const float*)d_in[14];
    const float* Wcls    = (const float*)d_in[15];
    const float* bcls    = (const float*)d_in[16];
    float* out = (float*)d_out;
    (void)in_sizes; (void)n_in; (void)out_size;

    float *gx, *o1, *o2;
    cudaGetSymbolAddress((void**)&gx, g_gx);
    cudaGetSymbolAddress((void**)&o1, g_out1);
    cudaGetSymbolAddress((void**)&o2, g_out2);
    float* gxf = gx;
    float* gxb = gx + (size_t)Mn * 2048;

    const int recSmem = (512 * 36 + 32 * 128 + 32 * 128 + 8 * 128 + 128) * 4;
    cudaFuncSetAttribute(rec_persist, cudaFuncAttributeMaxDynamicSharedMemorySize, recSmem);

    const dim3 th(256);
    const dim3 gBig(512, 16);   // 128x128 tiles over [65536, 2048]

    zero_ctr<<<1, 32>>>();

    // ---- layer 1 ----
    gemm_k<128, true><<<gBig, th>>>(nullptr, x, emb, Wih_f1, b_f1, gxf, 2048, 256);
    gemm_k<128, true><<<gBig, th>>>(nullptr, x, emb, Wih_b1, b_b1, gxb, 2048, 256);
    rec_persist<<<128, th, recSmem>>>(gxf, gxb, Whh_f1, Whh_b1, lengths, o1, 0);

    // ---- layer 2 ----
    gemm_k<128, false><<<gBig, th>>>(o1, nullptr, nullptr, Wih_f2, b_f2, gxf, 2048, 1024);
    gemm_k<128, false><<<gBig, th>>>(o1, nullptr, nullptr, Wih_b2, b_b2, gxb, 2048, 1024);
    rec_persist<<<128, th, recSmem>>>(gxf, gxb, Whh_f2, Whh_b2, lengths, o2, 2);

    // ---- classifier ----
    gemm_k<64, false><<<dim3(512, 1), th>>>(o2, nullptr, nullptr, Wcls, bcls, out, 64, 1024);
}

// round 13
// speedup vs baseline: 1.0643x; 1.0643x over previous
#include <cuda_runtime.h>
#include <cstddef>

// BiLSTM tagger: B=128, T=512, V=50000, E=256, H=512, TAGS=64
#define Mn 65536
#define Tn 512
#define Hn 512

typedef unsigned long long ull;

// ---------------- static device scratch (no allocations allowed) ----------
__device__ float g_gx[2ULL * Mn * 2048];        // gx for fwd+bwd of current layer
__device__ float g_out1[(size_t)Mn * 1024];     // layer1 output [b][t][1024]
__device__ float g_out2[(size_t)Mn * 1024];     // layer2 output
__device__ float g_h[2][2][Hn * 128];           // [dir][parity][unit*128+batch]
__device__ unsigned g_ctr[4];                   // grid-barrier counters

// ---------------- f32x2 helpers (FFMA2 is PTX-only) ------------------------
__device__ __forceinline__ ull dup2(float v) {
    ull r; asm("mov.b64 %0, {%1, %1};" : "=l"(r) : "f"(v)); return r;
}
__device__ __forceinline__ ull pack2(float a, float b) {
    ull r; asm("mov.b64 %0, {%1, %2};" : "=l"(r) : "f"(a), "f"(b)); return r;
}
__device__ __forceinline__ ull ffma2(ull a, ull b, ull c) {
    ull d; asm("fma.rn.f32x2 %0, %1, %2, %3;" : "=l"(d) : "l"(a), "l"(b), "l"(c));
    return d;
}
__device__ __forceinline__ float2 unpk2(ull a) {
    float2 f; asm("mov.b64 {%0, %1}, %2;" : "=f"(f.x), "=f"(f.y) : "l"(a));
    return f;
}
__device__ __forceinline__ float fsig(float x) { return 1.0f / (1.0f + __expf(-x)); }

__global__ void zero_ctr() { if (threadIdx.x < 4) g_ctr[threadIdx.x] = 0u; }

// ===========================================================================
// GEMM: C[M,N] = A[M,K] @ W[N,K]^T + bias[N]
// 128(M) x BN(N) block tile, K-tile 16, 256 threads.
// Thread tile: 8 m-rows x NP n-pairs, accumulated in packed f32x2 (FFMA2):
//   m = m0 + ty + 16*i (ty = tid>>4, i<8)
//   n = n0 + 2*tx + 32*j, +1 (tx = tid&15, j<NP)    NP = BN/32
// 32 FFMA2 per warp per k (vs 64 FFMA scalar) -> 2x fma-pipe throughput.
// Next K-tile prefetched into registers to hide global latency.
// GATHER: A row m is emb[xidx[m]] (layer-1 embedding lookup fused).
// All dims are exact multiples of the tiles (M=65536, N in {2048,64},
// K in {256,1024}) -> no tails.
// ===========================================================================
template <int BN, bool GATHER>
__global__ void __launch_bounds__(256) gemm_k(
    const float* __restrict__ A, const int* __restrict__ xidx,
    const float* __restrict__ emb, const float* __restrict__ W,
    const float* __restrict__ bias, float* __restrict__ C,
    int N, int K)
{
    constexpr int BP = BN + 4;            // even pitch keeps 8B alignment
    constexpr int NP = BN / 32;           // n-pairs per thread
    __shared__ float As[16 * 132];
    __shared__ float Bs[16 * BP];

    const int tid = threadIdx.x;
    const int m0 = blockIdx.x * 128, n0 = blockIdx.y * BN;
    const int rA = tid >> 2, kq = (tid & 3) * 4;

    const float *pa0, *pa1;
    if (GATHER) {
        pa0 = emb + (size_t)xidx[m0 + rA] * K + kq;
        pa1 = emb + (size_t)xidx[m0 + rA + 64] * K + kq;
    } else {
        pa0 = A + (size_t)(m0 + rA) * K + kq;
        pa1 = A + (size_t)(m0 + rA + 64) * K + kq;
    }
    const float* pb0 = W + (size_t)(n0 + rA) * K + kq;
    const float* pb1 = (BN == 128) ? (W + (size_t)(n0 + rA + 64) * K + kq) : pb0;

    const int tx = tid & 15, ty = tid >> 4;

    // ---- init accumulators with bias pairs ----
    ull acc[8][NP];
#pragma unroll
    for (int j = 0; j < NP; ++j) {
        const int n = n0 + 2 * tx + 32 * j;
        ull b2 = pack2(__ldg(bias + n), __ldg(bias + n + 1));
#pragma unroll
        for (int i = 0; i < 8; ++i) acc[i][j] = b2;
    }

    const int KT = K >> 4;
    // ---- prefetch first tile ----
    float4 a0 = *(const float4*)pa0;
    float4 a1 = *(const float4*)pa1;
    float4 b0 = *(const float4*)pb0;
    float4 b1 = make_float4(0.f, 0.f, 0.f, 0.f);
    if (BN == 128) b1 = *(const float4*)pb1;

    for (int kt = 0; kt < KT; ++kt) {
        // ---- stage current tile to smem ----
        As[(kq + 0) * 132 + rA] = a0.x;  As[(kq + 1) * 132 + rA] = a0.y;
        As[(kq + 2) * 132 + rA] = a0.z;  As[(kq + 3) * 132 + rA] = a0.w;
        As[(kq + 0) * 132 + rA + 64] = a1.x;  As[(kq + 1) * 132 + rA + 64] = a1.y;
        As[(kq + 2) * 132 + rA + 64] = a1.z;  As[(kq + 3) * 132 + rA + 64] = a1.w;
        Bs[(kq + 0) * BP + rA] = b0.x;   Bs[(kq + 1) * BP + rA] = b0.y;
        Bs[(kq + 2) * BP + rA] = b0.z;   Bs[(kq + 3) * BP + rA] = b0.w;
        if (BN == 128) {
            Bs[(kq + 0) * BP + rA + 64] = b1.x;  Bs[(kq + 1) * BP + rA + 64] = b1.y;
            Bs[(kq + 2) * BP + rA + 64] = b1.z;  Bs[(kq + 3) * BP + rA + 64] = b1.w;
        }
        __syncthreads();

        // ---- prefetch next tile (overlaps the microkernel) ----
        if (kt + 1 < KT) {
            const int off = (kt + 1) * 16;
            a0 = *(const float4*)(pa0 + off);
            a1 = *(const float4*)(pa1 + off);
            b0 = *(const float4*)(pb0 + off);
            if (BN == 128) b1 = *(const float4*)(pb1 + off);
        }

        // ---- microkernel: 32 FFMA2 per warp per k ----
#pragma unroll
        for (int k = 0; k < 16; ++k) {
            ull bp[NP];
#pragma unroll
            for (int j = 0; j < NP; ++j)
                bp[j] = *(const ull*)&Bs[k * BP + 2 * tx + 32 * j];
#pragma unroll
            for (int i = 0; i < 8; ++i) {
                const ull av = dup2(As[k * 132 + ty + 16 * i]);
#pragma unroll
                for (int j = 0; j < NP; ++j)
                    acc[i][j] = ffma2(av, bp[j], acc[i][j]);
            }
        }
        __syncthreads();
    }

    // ---- epilogue ----
#pragma unroll
    for (int i = 0; i < 8; ++i) {
        float* cr = C + (size_t)(m0 + ty + 16 * i) * N + n0;
#pragma unroll
        for (int j = 0; j < NP; ++j) {
            float2 v = unpk2(acc[i][j]);
            *(float2*)(cr + 2 * tx + 32 * j) = v;
        }
    }
}

// ===========================================================================
// Persistent bidirectional LSTM layer (validated round 11, unchanged).
// Grid = 128 blocks x 256 threads, 1 block/SM (111 KB dyn smem).
// Block owns 8 hidden units (32 gate rows x 128 batch, K=512).
// ===========================================================================
__global__ void __launch_bounds__(256) rec_persist(
    const float* __restrict__ gxf, const float* __restrict__ gxb,
    const float* __restrict__ Wf, const float* __restrict__ Wb,
    const int* __restrict__ lengths, float* __restrict__ out, int ctrBase)
{
    extern __shared__ __align__(16) float sm[];
    float* Wst = sm;                      // 512*36 = 18432 floats
    float* Hs  = Wst + 512 * 36;          // 32*128 =  4096
    float* Gs  = Hs + 32 * 128;           // 32*128 =  4096
    float* cs  = Gs + 32 * 128;           // 8*128  =  1024
    int* slen  = (int*)(cs + 8 * 128);    // 128 ints

    const int tid = threadIdx.x;
    const int dir = blockIdx.x >> 6;
    const int u0  = (blockIdx.x & 63) * 8;
    const float* gx  = dir ? gxb : gxf;
    const float* Whh = dir ? Wb : Wf;
    unsigned* ctr = &g_ctr[ctrBase + dir];

    if (tid < 128) slen[tid] = lengths[tid];

    // ---- stage W_hh slice once: Wst[k][row], pitch 36 ----
#pragma unroll 4
    for (int rl = 0; rl < 32; ++rl) {
        const int grow = (rl >> 3) * Hn + u0 + (rl & 7);
        const float* wr = Whh + (size_t)grow * Hn;
        Wst[(size_t)tid * 36 + rl]         = wr[tid];
        Wst[(size_t)(tid + 256) * 36 + rl] = wr[tid + 256];
    }
    __syncthreads();

    const int ry = tid >> 5, bx = tid & 31;

    for (int s = 0; s < Tn; ++s) {
        // ---- acc init from gx (pre-barrier: registers only) ----
        ull acc[4][2];
#pragma unroll
        for (int i = 0; i < 4; ++i) {
            const int rl = 4 * ry + i;
            const int grow = (rl >> 3) * Hn + u0 + (rl & 7);
#pragma unroll
            for (int j = 0; j < 2; ++j) {
                float v[2];
#pragma unroll
                for (int e = 0; e < 2; ++e) {
                    const int b = 2 * bx + 64 * j + e;
                    const int L = slen[b];
                    const bool ok = (s < L);
                    const int t = ok ? (dir ? (L - 1 - s) : s) : 0;
                    v[e] = ok ? __ldg(gx + (size_t)(b * Tn + t) * 2048 + grow) : 0.0f;
                }
                acc[i][j] = pack2(v[0], v[1]);
            }
        }

        if (s > 0) {
            // ---- grid barrier: wait for all 64 blocks of this dir ----
            if (tid == 0) {
                const unsigned tgt = 64u * (unsigned)s;
                unsigned v;
                for (;;) {
                    asm volatile("ld.acquire.gpu.u32 %0, [%1];" : "=r"(v) : "l"(ctr));
                    if (v >= tgt) break;
                    __nanosleep(64);
                }
            }
            __syncthreads();

            // ---- recurrent gemv: += W_hh_slice @ h_prev, 16 chunks of 32 k ----
            const float* hp = &g_h[dir][(s - 1) & 1][0];
            for (int kc = 0; kc < 16; ++kc) {
                const float4* src = (const float4*)(hp + kc * 32 * 128);
                float4 hv[4];
#pragma unroll
                for (int i = 0; i < 4; ++i) hv[i] = __ldcg(src + tid + 256 * i);
                __syncthreads();           // previous chunk fully consumed
                float4* d4 = (float4*)Hs;
#pragma unroll
                for (int i = 0; i < 4; ++i) d4[tid + 256 * i] = hv[i];
                __syncthreads();

#pragma unroll 4
                for (int k = 0; k < 32; ++k) {
                    const float4 wv = *(const float4*)&Wst[(size_t)(kc * 32 + k) * 36 + 4 * ry];
                    const ull h0 = *(const ull*)&Hs[k * 128 + 2 * bx];
                    const ull h1 = *(const ull*)&Hs[k * 128 + 2 * bx + 64];
                    const ull w0 = dup2(wv.x), w1 = dup2(wv.y);
                    const ull w2 = dup2(wv.z), w3 = dup2(wv.w);
                    acc[0][0] = ffma2(w0, h0, acc[0][0]);
                    acc[0][1] = ffma2(w0, h1, acc[0][1]);
                    acc[1][0] = ffma2(w1, h0, acc[1][0]);
                    acc[1][1] = ffma2(w1, h1, acc[1][1]);
                    acc[2][0] = ffma2(w2, h0, acc[2][0]);
                    acc[2][1] = ffma2(w2, h1, acc[2][1]);
                    acc[3][0] = ffma2(w3, h0, acc[3][0]);
                    acc[3][1] = ffma2(w3, h1, acc[3][1]);
                }
            }
        }

        // ---- gates -> smem ----
#pragma unroll
        for (int i = 0; i < 4; ++i) {
            *(ull*)&Gs[(4 * ry + i) * 128 + 2 * bx]      = acc[i][0];
            *(ull*)&Gs[(4 * ry + i) * 128 + 2 * bx + 64] = acc[i][1];
        }
        __syncthreads();

        // ---- cell update: 8 units x 128 batch, 4 cells/thread ----
        float* hw = &g_h[dir][s & 1][0];
#pragma unroll
        for (int q = 0; q < 4; ++q) {
            const int cell = tid + 256 * q;
            const int u = cell >> 7, b = cell & 127;
            const int L = slen[b];
            float hval = 0.0f;
            int t = s;
            if (s < L) {
                const float gi = Gs[u * 128 + b];
                const float gf = Gs[(8 + u) * 128 + b];
                const float gg = Gs[(16 + u) * 128 + b];
                const float go = Gs[(24 + u) * 128 + b];
                const float cp = (s == 0) ? 0.0f : cs[cell];
                const float cn = fsig(gf) * cp + fsig(gi) * tanhf(gg);
                cs[cell] = cn;
                hval = fsig(go) * tanhf(cn);
                t = dir ? (L - 1 - s) : s;
            }
            hw[(u0 + u) * 128 + b] = hval;
            out[(size_t)(b * Tn + t) * 1024 + dir * Hn + u0 + u] = hval;
        }

        // ---- release: h for step s visible at gpu scope ----
        __syncthreads();
        if (tid == 0) {
            __threadfence();
            atomicAdd(ctr, 1u);
        }
    }
}

// ===========================================================================
extern "C" void kernel_launch(void* const* d_in, const int* in_sizes, int n_in,
                              void* d_out, int out_size)
{
    const int*   x       = (const int*)d_in[0];
    const int*   lengths = (const int*)d_in[1];
    const float* emb     = (const float*)d_in[2];
    const float* Wih_f1  = (const float*)d_in[3];
    const float* Whh_f1  = (const float*)d_in[4];
    const float* b_f1    = (const float*)d_in[5];
    const float* Wih_b1  = (const float*)d_in[6];
    const float* Whh_b1  = (const float*)d_in[7];
    const float* b_b1    = (const float*)d_in[8];
    const float* Wih_f2  = (const float*)d_in[9];
    const float* Whh_f2  = (const float*)d_in[10];
    const float* b_f2    = (const float*)d_in[11];
    const float* Wih_b2  = (const float*)d_in[12];
    const float* Whh_b2  = (const float*)d_in[13];
    const float* b_b2    = (const float*)d_in[14];
    const float* Wcls    = (const float*)d_in[15];
    const float* bcls    = (const float*)d_in[16];
    float* out = (float*)d_out;
    (void)in_sizes; (void)n_in; (void)out_size;

    float *gx, *o1, *o2;
    cudaGetSymbolAddress((void**)&gx, g_gx);
    cudaGetSymbolAddress((void**)&o1, g_out1);
    cudaGetSymbolAddress((void**)&o2, g_out2);
    float* gxf = gx;
    float* gxb = gx + (size_t)Mn * 2048;

    const int recSmem = (512 * 36 + 32 * 128 + 32 * 128 + 8 * 128 + 128) * 4;
    cudaFuncSetAttribute(rec_persist, cudaFuncAttributeMaxDynamicSharedMemorySize, recSmem);

    const dim3 th(256);
    const dim3 gBig(512, 16);   // 128x128 tiles over [65536, 2048]

    zero_ctr<<<1, 32>>>();

    // ---- layer 1 ----
    gemm_k<128, true><<<gBig, th>>>(nullptr, x, emb, Wih_f1, b_f1, gxf, 2048, 256);
    gemm_k<128, true><<<gBig, th>>>(nullptr, x, emb, Wih_b1, b_b1, gxb, 2048, 256);
    rec_persist<<<128, th, recSmem>>>(gxf, gxb, Whh_f1, Whh_b1, lengths, o1, 0);

    // ---- layer 2 ----
    gemm_k<128, false><<<gBig, th>>>(o1, nullptr, nullptr, Wih_f2, b_f2, gxf, 2048, 1024);
    gemm_k<128, false><<<gBig, th>>>(o1, nullptr, nullptr, Wih_b2, b_b2, gxb, 2048, 1024);
    rec_persist<<<128, th, recSmem>>>(gxf, gxb, Whh_f2, Whh_b2, lengths, o2, 2);

    // ---- classifier ----
    gemm_k<64, false><<<dim3(512, 1), th>>>(o2, nullptr, nullptr, Wcls, bcls, out, 64, 1024);
}

// round 16
// speedup vs baseline: 1.2567x; 1.1808x over previous
#include <cuda_runtime.h>
#include <cuda_bf16.h>
#include <cstddef>
#include <cstdint>

// BiLSTM tagger: B=128, T=512, V=50000, E=256, H=512, TAGS=64
#define Mn 65536
#define Tn 512
#define Hn 512

typedef unsigned long long ull;

// ---------------- static device scratch (no allocations allowed) ----------
__device__ float g_gx[2ULL * Mn * 2048];        // gx for fwd+bwd of current layer
__device__ float g_out1[(size_t)Mn * 1024];     // layer1 output [b][t][1024]
__device__ float g_out2[(size_t)Mn * 1024];     // layer2 output
__device__ float g_h[2][2][Hn * 128];           // [dir][parity][unit*128+batch]
__device__ unsigned g_ctr[4];                   // grid-barrier counters
// bf16 hi/lo split scratch
__device__ __nv_bfloat16 g_ah[(size_t)Mn * 1024];   // split A (layer2 input)
__device__ __nv_bfloat16 g_al[(size_t)Mn * 1024];
__device__ __nv_bfloat16 g_ebh[50000 * 256];        // split embedding
__device__ __nv_bfloat16 g_ebl[50000 * 256];
__device__ __nv_bfloat16 g_wh[2][2048 * 1024];      // split W_ih per dir
__device__ __nv_bfloat16 g_wl[2][2048 * 1024];

// ---------------- helpers ---------------------------------------------------
__device__ __forceinline__ ull dup2(float v) {
    ull r; asm("mov.b64 %0, {%1, %1};" : "=l"(r) : "f"(v)); return r;
}
__device__ __forceinline__ ull pack2(float a, float b) {
    ull r; asm("mov.b64 %0, {%1, %2};" : "=l"(r) : "f"(a), "f"(b)); return r;
}
__device__ __forceinline__ ull ffma2(ull a, ull b, ull c) {
    ull d; asm("fma.rn.f32x2 %0, %1, %2, %3;" : "=l"(d) : "l"(a), "l"(b), "l"(c));
    return d;
}
__device__ __forceinline__ float fsig(float x) { return 1.0f / (1.0f + __expf(-x)); }
__device__ __forceinline__ uint32_t smem_u32(const void* p) {
    uint32_t a;
    asm("{ .reg .u64 t; cvta.to.shared.u64 t, %1; cvt.u32.u64 %0, t; }"
        : "=r"(a) : "l"(p));
    return a;
}
__device__ __forceinline__ uint32_t cvt_bf16x2(float lo, float hi) {
    uint32_t r;
    asm("cvt.rn.bf16x2.f32 %0, %1, %2;" : "=r"(r) : "f"(hi), "f"(lo));
    return r;
}
__device__ __forceinline__ void ldm4(uint32_t* r, uint32_t addr) {
    asm volatile("ldmatrix.sync.aligned.m8n8.x4.shared.b16 {%0,%1,%2,%3}, [%4];"
        : "=r"(r[0]), "=r"(r[1]), "=r"(r[2]), "=r"(r[3]) : "r"(addr));
}
__device__ __forceinline__ void mma_bf16(float* c, const uint32_t* a, const uint32_t* b) {
    asm volatile(
        "mma.sync.aligned.m16n8k16.row.col.f32.bf16.bf16.f32 "
        "{%0,%1,%2,%3}, {%4,%5,%6,%7}, {%8,%9}, {%0,%1,%2,%3};"
        : "+f"(c[0]), "+f"(c[1]), "+f"(c[2]), "+f"(c[3])
        : "r"(a[0]), "r"(a[1]), "r"(a[2]), "r"(a[3]), "r"(b[0]), "r"(b[1]));
}

__global__ void zero_ctr() { if (threadIdx.x < 4) g_ctr[threadIdx.x] = 0u; }

// ===========================================================================
// Split fp32 -> bf16 (hi) + bf16 (residual lo). n4 = element_count / 4.
// ===========================================================================
__global__ void __launch_bounds__(256) split_k(
    const float* __restrict__ src, __nv_bfloat16* __restrict__ hi,
    __nv_bfloat16* __restrict__ lo, int n4)
{
    const int i = blockIdx.x * 256 + threadIdx.x;
    if (i >= n4) return;
    const float4 v = ((const float4*)src)[i];
    const float hx = __bfloat162float(__float2bfloat16(v.x));
    const float hy = __bfloat162float(__float2bfloat16(v.y));
    const float hz = __bfloat162float(__float2bfloat16(v.z));
    const float hw = __bfloat162float(__float2bfloat16(v.w));
    uint2 h, l;
    h.x = cvt_bf16x2(hx, hy);            h.y = cvt_bf16x2(hz, hw);
    l.x = cvt_bf16x2(v.x - hx, v.y - hy); l.y = cvt_bf16x2(v.z - hz, v.w - hw);
    ((uint2*)hi)[i] = h;
    ((uint2*)lo)[i] = l;
}

// ===========================================================================
// Tensor-core GEMM via mma.sync (bf16 split, 3 products, fp32 accum):
//   C[M, 2048] = A[M,K] @ W[2048,K]^T + bias
// CTA: 128x128 tile, 256 threads = 8 warps as 2(m) x 4(n); warp tile 64x32.
// K chunk 32; smem: Ah/Al/Bh/Bl, 128 rows x 32 bf16, pitch 80B (ldmatrix
// row addresses at stride 80B cover all 32 banks -> conflict-free).
// Inputs pre-split to bf16 hi/lo; staging is pure 8B copies; next chunk
// prefetched into registers (LDG latency overlaps mma phase).
// grid = (16 n-blocks [fast], M/128) so consecutive CTAs share A rows in L2.
// GATHER: A row m = split-emb[xidx[m]] (layer-1 lookup fused).
// ===========================================================================
template <bool GATHER>
__global__ void __launch_bounds__(256, 1) gemm_mma(
    const __nv_bfloat16* __restrict__ Ahi, const __nv_bfloat16* __restrict__ Alo,
    const int* __restrict__ xidx,
    const __nv_bfloat16* __restrict__ Whi, const __nv_bfloat16* __restrict__ Wlo,
    const float* __restrict__ bias, float* __restrict__ C, int K)
{
    extern __shared__ __align__(16) char smc[];   // 4 * 10240 = 40960 B
    __shared__ int s_x[128];

    const int tid = threadIdx.x;
    const int n0 = blockIdx.x * 128, m0 = blockIdx.y * 128;
    const uint32_t uAh = smem_u32(smc);
    const uint32_t uAl = uAh + 10240, uBh = uAh + 20480, uBl = uAh + 30720;

    if (GATHER && tid < 128) s_x[tid] = xidx[m0 + tid];
    __syncthreads();

    // ---- staging map: 256 threads cover 128 rows x 32 k (4 rows each) ----
    const int r32 = tid >> 3, kb = tid & 7;
    size_t aRow[4], bRow[4];
#pragma unroll
    for (int i = 0; i < 4; ++i) {
        const int r = r32 + 32 * i;
        aRow[i] = (GATHER ? (size_t)s_x[r] : (size_t)(m0 + r)) * K;
        bRow[i] = (size_t)(n0 + r) * K;
    }

    // ---- mma lane mapping ----
    const int wid = tid >> 5, l = tid & 31;
    const int wm = wid >> 2, wn = wid & 3;
    const int lq = l >> 3, lr = l & 7;
    const int am = wm * 64 + (lq & 1) * 8 + lr;    // + 16i
    const int ak = (lq >> 1) * 8;                  // + 16ks
    const int bn = wn * 32 + (lq >> 1) * 8 + lr;   // + 16p
    const int bk = (lq & 1) * 8;
    const int row4 = l >> 2, col2 = (l & 3) * 2;

    // ---- accumulators, bias-initialized ----
    float c[4][4][4];
#pragma unroll
    for (int j = 0; j < 4; ++j) {
        const int n = n0 + wn * 32 + 8 * j + col2;
        const float b0 = __ldg(bias + n), b1 = __ldg(bias + n + 1);
#pragma unroll
        for (int i = 0; i < 4; ++i) {
            c[i][j][0] = b0; c[i][j][1] = b1; c[i][j][2] = b0; c[i][j][3] = b1;
        }
    }

    const int NC = K >> 5;
    uint2 pah[4], pal[4], pbh[4], pbl[4];
    {   // prefetch chunk 0
        const int kof = kb * 4;
#pragma unroll
        for (int i = 0; i < 4; ++i) {
            pah[i] = *(const uint2*)(Ahi + aRow[i] + kof);
            pal[i] = *(const uint2*)(Alo + aRow[i] + kof);
            pbh[i] = *(const uint2*)(Whi + bRow[i] + kof);
            pbl[i] = *(const uint2*)(Wlo + bRow[i] + kof);
        }
    }

    for (int cix = 0; cix < NC; ++cix) {
        // ---- commit staged registers to smem ----
#pragma unroll
        for (int i = 0; i < 4; ++i) {
            const int boff = 80 * (r32 + 32 * i) + 8 * kb;
            *(uint2*)(smc + boff)         = pah[i];
            *(uint2*)(smc + 10240 + boff) = pal[i];
            *(uint2*)(smc + 20480 + boff) = pbh[i];
            *(uint2*)(smc + 30720 + boff) = pbl[i];
        }
        __syncthreads();

        // ---- prefetch next chunk (overlaps mma below) ----
        if (cix + 1 < NC) {
            const int kof = (cix + 1) * 32 + kb * 4;
#pragma unroll
            for (int i = 0; i < 4; ++i) {
                pah[i] = *(const uint2*)(Ahi + aRow[i] + kof);
                pal[i] = *(const uint2*)(Alo + aRow[i] + kof);
                pbh[i] = *(const uint2*)(Whi + bRow[i] + kof);
                pbl[i] = *(const uint2*)(Wlo + bRow[i] + kof);
            }
        }

        // ---- mma: 2 k16 steps x (Ah*Bh + Ah*Bl + Al*Bh) ----
#pragma unroll
        for (int ks = 0; ks < 2; ++ks) {
            uint32_t ah[4][4], al_[4][4], bh[2][4], bl[2][4];
#pragma unroll
            for (int i = 0; i < 4; ++i) {
                const uint32_t off = 80u * (uint32_t)(am + 16 * i) + 2u * (uint32_t)(ak + 16 * ks);
                ldm4(ah[i], uAh + off);
                ldm4(al_[i], uAl + off);
            }
#pragma unroll
            for (int p = 0; p < 2; ++p) {
                const uint32_t off = 80u * (uint32_t)(bn + 16 * p) + 2u * (uint32_t)(bk + 16 * ks);
                ldm4(bh[p], uBh + off);
                ldm4(bl[p], uBl + off);
            }
#pragma unroll
            for (int i = 0; i < 4; ++i)
#pragma unroll
                for (int j = 0; j < 4; ++j) {
                    const uint32_t* bhp = &bh[j >> 1][2 * (j & 1)];
                    const uint32_t* blp = &bl[j >> 1][2 * (j & 1)];
                    mma_bf16(c[i][j], ah[i], bhp);
                    mma_bf16(c[i][j], ah[i], blp);
                    mma_bf16(c[i][j], al_[i], bhp);
                }
        }
        __syncthreads();
    }

    // ---- epilogue ----
#pragma unroll
    for (int i = 0; i < 4; ++i) {
        const int m = m0 + wm * 64 + 16 * i + row4;
#pragma unroll
        for (int j = 0; j < 4; ++j) {
            const int n = n0 + wn * 32 + 8 * j + col2;
            *(float2*)(C + (size_t)m * 2048 + n)       = make_float2(c[i][j][0], c[i][j][1]);
            *(float2*)(C + (size_t)(m + 8) * 2048 + n) = make_float2(c[i][j][2], c[i][j][3]);
        }
    }
}

// ===========================================================================
// SIMT FFMA2 GEMM — classifier only (N=64, K=1024).
// ===========================================================================
__global__ void __launch_bounds__(256) gemm_cls(
    const float* __restrict__ A, const float* __restrict__ W,
    const float* __restrict__ bias, float* __restrict__ C,
    int N, int K)
{
    constexpr int BN = 64, BP = BN + 4, NP = BN / 32;
    __shared__ float As[16 * 132];
    __shared__ float Bs[16 * BP];

    const int tid = threadIdx.x;
    const int m0 = blockIdx.x * 128, n0 = 0;
    const int rA = tid >> 2, kq = (tid & 3) * 4;

    const float* pa0 = A + (size_t)(m0 + rA) * K + kq;
    const float* pa1 = A + (size_t)(m0 + rA + 64) * K + kq;
    const float* pb0 = W + (size_t)(n0 + rA) * K + kq;

    const int tx = tid & 15, ty = tid >> 4;

    ull acc[8][NP];
#pragma unroll
    for (int j = 0; j < NP; ++j) {
        const int n = n0 + 2 * tx + 32 * j;
        ull b2 = pack2(__ldg(bias + n), __ldg(bias + n + 1));
#pragma unroll
        for (int i = 0; i < 8; ++i) acc[i][j] = b2;
    }

    const int KT = K >> 4;
    float4 a0 = *(const float4*)pa0;
    float4 a1 = *(const float4*)pa1;
    float4 b0 = *(const float4*)pb0;

    for (int kt = 0; kt < KT; ++kt) {
        As[(kq + 0) * 132 + rA] = a0.x;  As[(kq + 1) * 132 + rA] = a0.y;
        As[(kq + 2) * 132 + rA] = a0.z;  As[(kq + 3) * 132 + rA] = a0.w;
        As[(kq + 0) * 132 + rA + 64] = a1.x;  As[(kq + 1) * 132 + rA + 64] = a1.y;
        As[(kq + 2) * 132 + rA + 64] = a1.z;  As[(kq + 3) * 132 + rA + 64] = a1.w;
        Bs[(kq + 0) * BP + rA] = b0.x;   Bs[(kq + 1) * BP + rA] = b0.y;
        Bs[(kq + 2) * BP + rA] = b0.z;   Bs[(kq + 3) * BP + rA] = b0.w;
        __syncthreads();

        if (kt + 1 < KT) {
            const int off = (kt + 1) * 16;
            a0 = *(const float4*)(pa0 + off);
            a1 = *(const float4*)(pa1 + off);
            b0 = *(const float4*)(pb0 + off);
        }

#pragma unroll
        for (int k = 0; k < 16; ++k) {
            ull bp[NP];
#pragma unroll
            for (int j = 0; j < NP; ++j)
                bp[j] = *(const ull*)&Bs[k * BP + 2 * tx + 32 * j];
#pragma unroll
            for (int i = 0; i < 8; ++i) {
                const ull av = dup2(As[k * 132 + ty + 16 * i]);
#pragma unroll
                for (int j = 0; j < NP; ++j)
                    acc[i][j] = ffma2(av, bp[j], acc[i][j]);
            }
        }
        __syncthreads();
    }

#pragma unroll
    for (int i = 0; i < 8; ++i) {
        float* cr = C + (size_t)(m0 + ty + 16 * i) * N + n0;
#pragma unroll
        for (int j = 0; j < NP; ++j) {
            float2 v;
            asm("mov.b64 {%0, %1}, %2;" : "=f"(v.x), "=f"(v.y) : "l"(acc[i][j]));
            *(float2*)(cr + 2 * tx + 32 * j) = v;
        }
    }
}

// ===========================================================================
// Persistent bidirectional LSTM layer (validated rounds 11/13, unchanged).
// ===========================================================================
__global__ void __launch_bounds__(256) rec_persist(
    const float* __restrict__ gxf, const float* __restrict__ gxb,
    const float* __restrict__ Wf, const float* __restrict__ Wb,
    const int* __restrict__ lengths, float* __restrict__ out, int ctrBase)
{
    extern __shared__ __align__(16) float sm[];
    float* Wst = sm;                      // 512*36 = 18432 floats
    float* Hs  = Wst + 512 * 36;          // 32*128 =  4096
    float* Gs  = Hs + 32 * 128;           // 32*128 =  4096
    float* cs  = Gs + 32 * 128;           // 8*128  =  1024
    int* slen  = (int*)(cs + 8 * 128);    // 128 ints

    const int tid = threadIdx.x;
    const int dir = blockIdx.x >> 6;
    const int u0  = (blockIdx.x & 63) * 8;
    const float* gx  = dir ? gxb : gxf;
    const float* Whh = dir ? Wb : Wf;
    unsigned* ctr = &g_ctr[ctrBase + dir];

    if (tid < 128) slen[tid] = lengths[tid];

#pragma unroll 4
    for (int rl = 0; rl < 32; ++rl) {
        const int grow = (rl >> 3) * Hn + u0 + (rl & 7);
        const float* wr = Whh + (size_t)grow * Hn;
        Wst[(size_t)tid * 36 + rl]         = wr[tid];
        Wst[(size_t)(tid + 256) * 36 + rl] = wr[tid + 256];
    }
    __syncthreads();

    const int ry = tid >> 5, bx = tid & 31;

    for (int s = 0; s < Tn; ++s) {
        ull acc[4][2];
#pragma unroll
        for (int i = 0; i < 4; ++i) {
            const int rl = 4 * ry + i;
            const int grow = (rl >> 3) * Hn + u0 + (rl & 7);
#pragma unroll
            for (int j = 0; j < 2; ++j) {
                float v[2];
#pragma unroll
                for (int e = 0; e < 2; ++e) {
                    const int b = 2 * bx + 64 * j + e;
                    const int L = slen[b];
                    const bool ok = (s < L);
                    const int t = ok ? (dir ? (L - 1 - s) : s) : 0;
                    v[e] = ok ? __ldg(gx + (size_t)(b * Tn + t) * 2048 + grow) : 0.0f;
                }
                acc[i][j] = pack2(v[0], v[1]);
            }
        }

        if (s > 0) {
            if (tid == 0) {
                const unsigned tgt = 64u * (unsigned)s;
                unsigned v;
                for (;;) {
                    asm volatile("ld.acquire.gpu.u32 %0, [%1];" : "=r"(v) : "l"(ctr));
                    if (v >= tgt) break;
                    __nanosleep(64);
                }
            }
            __syncthreads();

            const float* hp = &g_h[dir][(s - 1) & 1][0];
            for (int kc = 0; kc < 16; ++kc) {
                const float4* src = (const float4*)(hp + kc * 32 * 128);
                float4 hv[4];
#pragma unroll
                for (int i = 0; i < 4; ++i) hv[i] = __ldcg(src + tid + 256 * i);
                __syncthreads();
                float4* d4 = (float4*)Hs;
#pragma unroll
                for (int i = 0; i < 4; ++i) d4[tid + 256 * i] = hv[i];
                __syncthreads();

#pragma unroll 4
                for (int k = 0; k < 32; ++k) {
                    const float4 wv = *(const float4*)&Wst[(size_t)(kc * 32 + k) * 36 + 4 * ry];
                    const ull h0 = *(const ull*)&Hs[k * 128 + 2 * bx];
                    const ull h1 = *(const ull*)&Hs[k * 128 + 2 * bx + 64];
                    const ull w0 = dup2(wv.x), w1 = dup2(wv.y);
                    const ull w2 = dup2(wv.z), w3 = dup2(wv.w);
                    acc[0][0] = ffma2(w0, h0, acc[0][0]);
                    acc[0][1] = ffma2(w0, h1, acc[0][1]);
                    acc[1][0] = ffma2(w1, h0, acc[1][0]);
                    acc[1][1] = ffma2(w1, h1, acc[1][1]);
                    acc[2][0] = ffma2(w2, h0, acc[2][0]);
                    acc[2][1] = ffma2(w2, h1, acc[2][1]);
                    acc[3][0] = ffma2(w3, h0, acc[3][0]);
                    acc[3][1] = ffma2(w3, h1, acc[3][1]);
                }
            }
        }

#pragma unroll
        for (int i = 0; i < 4; ++i) {
            *(ull*)&Gs[(4 * ry + i) * 128 + 2 * bx]      = acc[i][0];
            *(ull*)&Gs[(4 * ry + i) * 128 + 2 * bx + 64] = acc[i][1];
        }
        __syncthreads();

        float* hw = &g_h[dir][s & 1][0];
#pragma unroll
        for (int q = 0; q < 4; ++q) {
            const int cell = tid + 256 * q;
            const int u = cell >> 7, b = cell & 127;
            const int L = slen[b];
            float hval = 0.0f;
            int t = s;
            if (s < L) {
                const float gi = Gs[u * 128 + b];
                const float gf = Gs[(8 + u) * 128 + b];
                const float gg = Gs[(16 + u) * 128 + b];
                const float go = Gs[(24 + u) * 128 + b];
                const float cp = (s == 0) ? 0.0f : cs[cell];
                const float cn = fsig(gf) * cp + fsig(gi) * tanhf(gg);
                cs[cell] = cn;
                hval = fsig(go) * tanhf(cn);
                t = dir ? (L - 1 - s) : s;
            }
            hw[(u0 + u) * 128 + b] = hval;
            out[(size_t)(b * Tn + t) * 1024 + dir * Hn + u0 + u] = hval;
        }

        __syncthreads();
        if (tid == 0) {
            __threadfence();
            atomicAdd(ctr, 1u);
        }
    }
}

// ===========================================================================
extern "C" void kernel_launch(void* const* d_in, const int* in_sizes, int n_in,
                              void* d_out, int out_size)
{
    const int*   x       = (const int*)d_in[0];
    const int*   lengths = (const int*)d_in[1];
    const float* emb     = (const float*)d_in[2];
    const float* Wih_f1  = (const float*)d_in[3];
    const float* Whh_f1  = (const float*)d_in[4];
    const float* b_f1    = (const float*)d_in[5];
    const float* Wih_b1  = (const float*)d_in[6];
    const float* Whh_b1  = (const float*)d_in[7];
    const float* b_b1    = (const float*)d_in[8];
    const float* Wih_f2  = (const float*)d_in[9];
    const float* Whh_f2  = (const float*)d_in[10];
    const float* b_f2    = (const float*)d_in[11];
    const float* Wih_b2  = (const float*)d_in[12];
    const float* Whh_b2  = (const float*)d_in[13];
    const float* b_b2    = (const float*)d_in[14];
    const float* Wcls    = (const float*)d_in[15];
    const float* bcls    = (const float*)d_in[16];
    float* out = (float*)d_out;
    (void)in_sizes; (void)n_in; (void)out_size;

    float *gx, *o1, *o2;
    cudaGetSymbolAddress((void**)&gx, g_gx);
    cudaGetSymbolAddress((void**)&o1, g_out1);
    cudaGetSymbolAddress((void**)&o2, g_out2);
    __nv_bfloat16 *ah, *al, *ebh, *ebl, *wh, *wl;
    cudaGetSymbolAddress((void**)&ah, g_ah);
    cudaGetSymbolAddress((void**)&al, g_al);
    cudaGetSymbolAddress((void**)&ebh, g_ebh);
    cudaGetSymbolAddress((void**)&ebl, g_ebl);
    cudaGetSymbolAddress((void**)&wh, g_wh);
    cudaGetSymbolAddress((void**)&wl, g_wl);
    __nv_bfloat16* wh0 = wh;               __nv_bfloat16* wl0 = wl;
    __nv_bfloat16* wh1 = wh + 2048 * 1024; __nv_bfloat16* wl1 = wl + 2048 * 1024;
    float* gxf = gx;
    float* gxb = gx + (size_t)Mn * 2048;

    const int recSmem = (512 * 36 + 32 * 128 + 32 * 128 + 8 * 128 + 128) * 4;
    cudaFuncSetAttribute(rec_persist, cudaFuncAttributeMaxDynamicSharedMemorySize, recSmem);
    cudaFuncSetAttribute(gemm_mma<true>,  cudaFuncAttributeMaxDynamicSharedMemorySize, 40960);
    cudaFuncSetAttribute(gemm_mma<false>, cudaFuncAttributeMaxDynamicSharedMemorySize, 40960);

    const dim3 tcg(16, 512);   // n-blocks fast -> A rows shared in L2

    zero_ctr<<<1, 32>>>();

    // ---- one-time splits for layer 1 ----
    split_k<<<12500, 256>>>(emb, ebh, ebl, 50000 * 256 / 4);
    split_k<<<512, 256>>>(Wih_f1, wh0, wl0, 2048 * 256 / 4);
    split_k<<<512, 256>>>(Wih_b1, wh1, wl1, 2048 * 256 / 4);

    // ---- layer 1 (K=256, embedding gather fused) ----
    gemm_mma<true><<<tcg, 256, 40960>>>(ebh, ebl, x, wh0, wl0, b_f1, gxf, 256);
    gemm_mma<true><<<tcg, 256, 40960>>>(ebh, ebl, x, wh1, wl1, b_b1, gxb, 256);
    rec_persist<<<128, 256, recSmem>>>(gxf, gxb, Whh_f1, Whh_b1, lengths, o1, 0);

    // ---- splits for layer 2 ----
    split_k<<<65536, 256>>>(o1, ah, al, Mn * 1024 / 4);
    split_k<<<2048, 256>>>(Wih_f2, wh0, wl0, 2048 * 1024 / 4);
    split_k<<<2048, 256>>>(Wih_b2, wh1, wl1, 2048 * 1024 / 4);

    // ---- layer 2 (K=1024) ----
    gemm_mma<false><<<tcg, 256, 40960>>>(ah, al, nullptr, wh0, wl0, b_f2, gxf, 1024);
    gemm_mma<false><<<tcg, 256, 40960>>>(ah, al, nullptr, wh1, wl1, b_b2, gxb, 1024);
    rec_persist<<<128, 256, recSmem>>>(gxf, gxb, Whh_f2, Whh_b2, lengths, o2, 2);

    // ---- classifier ----
    gemm_cls<<<512, 256>>>(o2, Wcls, bcls, out, 64, 1024);
}

// round 17
// speedup vs baseline: 1.2817x; 1.0199x over previous
#include <cuda_runtime.h>
#include <cuda_bf16.h>
#include <cstddef>
#include <cstdint>

// BiLSTM tagger: B=128, T=512, V=50000, E=256, H=512, TAGS=64
#define Mn 65536
#define Tn 512
#define Hn 512

typedef unsigned long long ull;

// ---------------- static device scratch (no allocations allowed) ----------
__device__ float g_gx[2ULL * Mn * 2048];        // gx for fwd+bwd of current layer
__device__ float g_out1[(size_t)Mn * 1024];     // layer1 output [b][t][1024]
__device__ float g_out2[(size_t)Mn * 1024];     // layer2 output
__device__ float g_h[2][2][Hn * 128];           // [dir][parity][unit*128+batch]
__device__ unsigned g_ctr[4];                   // grid-barrier counters
// bf16 hi/lo split scratch
__device__ __nv_bfloat16 g_ah[(size_t)Mn * 1024];   // split A (layer2 input)
__device__ __nv_bfloat16 g_al[(size_t)Mn * 1024];
__device__ __nv_bfloat16 g_ebh[50000 * 256];        // split embedding
__device__ __nv_bfloat16 g_ebl[50000 * 256];
__device__ __nv_bfloat16 g_wh[2][2048 * 1024];      // split W_ih per dir
__device__ __nv_bfloat16 g_wl[2][2048 * 1024];

// ---------------- helpers ---------------------------------------------------
__device__ __forceinline__ ull dup2(float v) {
    ull r; asm("mov.b64 %0, {%1, %1};" : "=l"(r) : "f"(v)); return r;
}
__device__ __forceinline__ ull pack2(float a, float b) {
    ull r; asm("mov.b64 %0, {%1, %2};" : "=l"(r) : "f"(a), "f"(b)); return r;
}
__device__ __forceinline__ ull ffma2(ull a, ull b, ull c) {
    ull d; asm("fma.rn.f32x2 %0, %1, %2, %3;" : "=l"(d) : "l"(a), "l"(b), "l"(c));
    return d;
}
__device__ __forceinline__ float fsig(float x) { return 1.0f / (1.0f + __expf(-x)); }
__device__ __forceinline__ uint32_t smem_u32(const void* p) {
    uint32_t a;
    asm("{ .reg .u64 t; cvta.to.shared.u64 t, %1; cvt.u32.u64 %0, t; }"
        : "=r"(a) : "l"(p));
    return a;
}
__device__ __forceinline__ uint32_t cvt_bf16x2(float lo, float hi) {
    uint32_t r;
    asm("cvt.rn.bf16x2.f32 %0, %1, %2;" : "=r"(r) : "f"(hi), "f"(lo));
    return r;
}
__device__ __forceinline__ void ldm4(uint32_t* r, uint32_t addr) {
    asm volatile("ldmatrix.sync.aligned.m8n8.x4.shared.b16 {%0,%1,%2,%3}, [%4];"
        : "=r"(r[0]), "=r"(r[1]), "=r"(r[2]), "=r"(r[3]) : "r"(addr));
}
__device__ __forceinline__ void mma_bf16(float* c, const uint32_t* a, const uint32_t* b) {
    asm volatile(
        "mma.sync.aligned.m16n8k16.row.col.f32.bf16.bf16.f32 "
        "{%0,%1,%2,%3}, {%4,%5,%6,%7}, {%8,%9}, {%0,%1,%2,%3};"
        : "+f"(c[0]), "+f"(c[1]), "+f"(c[2]), "+f"(c[3])
        : "r"(a[0]), "r"(a[1]), "r"(a[2]), "r"(a[3]), "r"(b[0]), "r"(b[1]));
}
__device__ __forceinline__ void cp16(uint32_t dst, const void* src) {
    asm volatile("cp.async.cg.shared.global [%0], [%1], 16;"
        :: "r"(dst), "l"(src) : "memory");
}
__device__ __forceinline__ void cp_commit() {
    asm volatile("cp.async.commit_group;" ::: "memory");
}

__global__ void zero_ctr() { if (threadIdx.x < 4) g_ctr[threadIdx.x] = 0u; }

// ===========================================================================
// Split fp32 -> bf16 (hi) + bf16 (residual lo). n4 = element_count / 4.
// ===========================================================================
__global__ void __launch_bounds__(256) split_k(
    const float* __restrict__ src, __nv_bfloat16* __restrict__ hi,
    __nv_bfloat16* __restrict__ lo, int n4)
{
    const int i = blockIdx.x * 256 + threadIdx.x;
    if (i >= n4) return;
    const float4 v = ((const float4*)src)[i];
    const float hx = __bfloat162float(__float2bfloat16(v.x));
    const float hy = __bfloat162float(__float2bfloat16(v.y));
    const float hz = __bfloat162float(__float2bfloat16(v.z));
    const float hw = __bfloat162float(__float2bfloat16(v.w));
    uint2 h, l;
    h.x = cvt_bf16x2(hx, hy);            h.y = cvt_bf16x2(hz, hw);
    l.x = cvt_bf16x2(v.x - hx, v.y - hy); l.y = cvt_bf16x2(v.z - hz, v.w - hw);
    ((uint2*)hi)[i] = h;
    ((uint2*)lo)[i] = l;
}

// ===========================================================================
// Tensor-core GEMM via mma.sync (bf16 split, 3 products, fp32 accum):
//   C[M, 2048] = A[M,K] @ W[2048,K]^T + bias
// CTA: 128x128 tile, 512 threads = 16 warps as 4(m) x 4(n); warp tile 32x32
// (acc 32 regs -> ~90 regs/thread -> 4 warps resident per SMSP: latency hiding).
// K chunk 32; smem double-buffered (2 x 4 arrays x 128 rows x 32 bf16,
// pitch 80B: ldmatrix row addresses stride 20 words cover all banks).
// cp.async.cg 16B staging, 2-deep pipeline: load chunk c+1 overlaps mma c.
// grid = (16 n-blocks [fast], M/128) so consecutive CTAs share A rows in L2.
// GATHER: A row m = split-emb[xidx[m]] (layer-1 lookup fused).
// ===========================================================================
#define ARR_SZ 10240
#define BUF_SZ 40960
template <bool GATHER>
__global__ void __launch_bounds__(512, 1) gemm_mma(
    const __nv_bfloat16* __restrict__ Ahi, const __nv_bfloat16* __restrict__ Alo,
    const int* __restrict__ xidx,
    const __nv_bfloat16* __restrict__ Whi, const __nv_bfloat16* __restrict__ Wlo,
    const float* __restrict__ bias, float* __restrict__ C, int K)
{
    extern __shared__ __align__(16) char smc[];   // 2 * 40960 B
    __shared__ int s_x[128];

    const int tid = threadIdx.x;
    const int n0 = blockIdx.x * 128, m0 = blockIdx.y * 128;
    const uint32_t sbase = smem_u32(smc);

    if (GATHER && tid < 128) s_x[tid] = xidx[m0 + tid];
    __syncthreads();

    // ---- staging map: 512 threads = 128 rows x 4 k-segments (16B each) ----
    const int srow = tid >> 2, kseg = tid & 3;
    const size_t aR = (GATHER ? (size_t)s_x[srow] : (size_t)(m0 + srow)) * K;
    const size_t bR = (size_t)(n0 + srow) * K;
    const uint32_t dOff = (uint32_t)(80 * srow + 16 * kseg);

    const int NC = K >> 5;

    // issue cp.async for chunk c into buffer c&1
    auto issue = [&](int c) {
        const uint32_t db = sbase + (uint32_t)(c & 1) * BUF_SZ + dOff;
        const int kof = c * 32 + kseg * 8;
        cp16(db,                Ahi + aR + kof);
        cp16(db + ARR_SZ,       Alo + aR + kof);
        cp16(db + 2 * ARR_SZ,   Whi + bR + kof);
        cp16(db + 3 * ARR_SZ,   Wlo + bR + kof);
        cp_commit();
    };

    // ---- mma lane mapping (recipe validated round 16; bases for 32x32) ----
    const int wid = tid >> 5, l = tid & 31;
    const int wm = wid >> 2, wn = wid & 3;
    const int lq = l >> 3, lr = l & 7;
    const int am = wm * 32 + (lq & 1) * 8 + lr;    // + 16i
    const int ak = (lq >> 1) * 8;                  // + 16ks
    const int bn = wn * 32 + (lq >> 1) * 8 + lr;   // + 16p
    const int bk = (lq & 1) * 8;
    const int row4 = l >> 2, col2 = (l & 3) * 2;

    // ---- accumulators, bias-initialized ----
    float c[2][4][4];
#pragma unroll
    for (int j = 0; j < 4; ++j) {
        const int n = n0 + wn * 32 + 8 * j + col2;
        const float b0 = __ldg(bias + n), b1 = __ldg(bias + n + 1);
#pragma unroll
        for (int i = 0; i < 2; ++i) {
            c[i][j][0] = b0; c[i][j][1] = b1; c[i][j][2] = b0; c[i][j][3] = b1;
        }
    }

    // ---- 2-deep pipeline prologue ----
    issue(0);
    if (NC > 1) issue(1);

    for (int cix = 0; cix < NC; ++cix) {
        if (cix + 1 < NC) asm volatile("cp.async.wait_group 1;" ::: "memory");
        else              asm volatile("cp.async.wait_group 0;" ::: "memory");
        __syncthreads();

        const uint32_t ub = sbase + (uint32_t)(cix & 1) * BUF_SZ;
#pragma unroll
        for (int ks = 0; ks < 2; ++ks) {
            uint32_t ah[2][4], al_[2][4], bh[2][4], bl[2][4];
#pragma unroll
            for (int i = 0; i < 2; ++i) {
                const uint32_t off = 80u * (uint32_t)(am + 16 * i) + 2u * (uint32_t)(ak + 16 * ks);
                ldm4(ah[i], ub + off);
                ldm4(al_[i], ub + ARR_SZ + off);
            }
#pragma unroll
            for (int p = 0; p < 2; ++p) {
                const uint32_t off = 80u * (uint32_t)(bn + 16 * p) + 2u * (uint32_t)(bk + 16 * ks);
                ldm4(bh[p], ub + 2 * ARR_SZ + off);
                ldm4(bl[p], ub + 3 * ARR_SZ + off);
            }
#pragma unroll
            for (int i = 0; i < 2; ++i)
#pragma unroll
                for (int j = 0; j < 4; ++j) {
                    const uint32_t* bhp = &bh[j >> 1][2 * (j & 1)];
                    const uint32_t* blp = &bl[j >> 1][2 * (j & 1)];
                    mma_bf16(c[i][j], ah[i], bhp);
                    mma_bf16(c[i][j], ah[i], blp);
                    mma_bf16(c[i][j], al_[i], bhp);
                }
        }
        __syncthreads();
        if (cix + 2 < NC) issue(cix + 2);
    }

    // ---- epilogue ----
#pragma unroll
    for (int i = 0; i < 2; ++i) {
        const int m = m0 + wm * 32 + 16 * i + row4;
#pragma unroll
        for (int j = 0; j < 4; ++j) {
            const int n = n0 + wn * 32 + 8 * j + col2;
            *(float2*)(C + (size_t)m * 2048 + n)       = make_float2(c[i][j][0], c[i][j][1]);
            *(float2*)(C + (size_t)(m + 8) * 2048 + n) = make_float2(c[i][j][2], c[i][j][3]);
        }
    }
}

// ===========================================================================
// SIMT FFMA2 GEMM — classifier only (N=64, K=1024).
// ===========================================================================
__global__ void __launch_bounds__(256) gemm_cls(
    const float* __restrict__ A, const float* __restrict__ W,
    const float* __restrict__ bias, float* __restrict__ C,
    int N, int K)
{
    constexpr int BN = 64, BP = BN + 4, NP = BN / 32;
    __shared__ float As[16 * 132];
    __shared__ float Bs[16 * BP];

    const int tid = threadIdx.x;
    const int m0 = blockIdx.x * 128, n0 = 0;
    const int rA = tid >> 2, kq = (tid & 3) * 4;

    const float* pa0 = A + (size_t)(m0 + rA) * K + kq;
    const float* pa1 = A + (size_t)(m0 + rA + 64) * K + kq;
    const float* pb0 = W + (size_t)(n0 + rA) * K + kq;

    const int tx = tid & 15, ty = tid >> 4;

    ull acc[8][NP];
#pragma unroll
    for (int j = 0; j < NP; ++j) {
        const int n = n0 + 2 * tx + 32 * j;
        ull b2 = pack2(__ldg(bias + n), __ldg(bias + n + 1));
#pragma unroll
        for (int i = 0; i < 8; ++i) acc[i][j] = b2;
    }

    const int KT = K >> 4;
    float4 a0 = *(const float4*)pa0;
    float4 a1 = *(const float4*)pa1;
    float4 b0 = *(const float4*)pb0;

    for (int kt = 0; kt < KT; ++kt) {
        As[(kq + 0) * 132 + rA] = a0.x;  As[(kq + 1) * 132 + rA] = a0.y;
        As[(kq + 2) * 132 + rA] = a0.z;  As[(kq + 3) * 132 + rA] = a0.w;
        As[(kq + 0) * 132 + rA + 64] = a1.x;  As[(kq + 1) * 132 + rA + 64] = a1.y;
        As[(kq + 2) * 132 + rA + 64] = a1.z;  As[(kq + 3) * 132 + rA + 64] = a1.w;
        Bs[(kq + 0) * BP + rA] = b0.x;   Bs[(kq + 1) * BP + rA] = b0.y;
        Bs[(kq + 2) * BP + rA] = b0.z;   Bs[(kq + 3) * BP + rA] = b0.w;
        __syncthreads();

        if (kt + 1 < KT) {
            const int off = (kt + 1) * 16;
            a0 = *(const float4*)(pa0 + off);
            a1 = *(const float4*)(pa1 + off);
            b0 = *(const float4*)(pb0 + off);
        }

#pragma unroll
        for (int k = 0; k < 16; ++k) {
            ull bp[NP];
#pragma unroll
            for (int j = 0; j < NP; ++j)
                bp[j] = *(const ull*)&Bs[k * BP + 2 * tx + 32 * j];
#pragma unroll
            for (int i = 0; i < 8; ++i) {
                const ull av = dup2(As[k * 132 + ty + 16 * i]);
#pragma unroll
                for (int j = 0; j < NP; ++j)
                    acc[i][j] = ffma2(av, bp[j], acc[i][j]);
            }
        }
        __syncthreads();
    }

#pragma unroll
    for (int i = 0; i < 8; ++i) {
        float* cr = C + (size_t)(m0 + ty + 16 * i) * N + n0;
#pragma unroll
        for (int j = 0; j < NP; ++j) {
            float2 v;
            asm("mov.b64 {%0, %1}, %2;" : "=f"(v.x), "=f"(v.y) : "l"(acc[i][j]));
            *(float2*)(cr + 2 * tx + 32 * j) = v;
        }
    }
}

// ===========================================================================
// Persistent bidirectional LSTM layer (validated rounds 11/13, unchanged).
// ===========================================================================
__global__ void __launch_bounds__(256) rec_persist(
    const float* __restrict__ gxf, const float* __restrict__ gxb,
    const float* __restrict__ Wf, const float* __restrict__ Wb,
    const int* __restrict__ lengths, float* __restrict__ out, int ctrBase)
{
    extern __shared__ __align__(16) float sm[];
    float* Wst = sm;                      // 512*36 = 18432 floats
    float* Hs  = Wst + 512 * 36;          // 32*128 =  4096
    float* Gs  = Hs + 32 * 128;           // 32*128 =  4096
    float* cs  = Gs + 32 * 128;           // 8*128  =  1024
    int* slen  = (int*)(cs + 8 * 128);    // 128 ints

    const int tid = threadIdx.x;
    const int dir = blockIdx.x >> 6;
    const int u0  = (blockIdx.x & 63) * 8;
    const float* gx  = dir ? gxb : gxf;
    const float* Whh = dir ? Wb : Wf;
    unsigned* ctr = &g_ctr[ctrBase + dir];

    if (tid < 128) slen[tid] = lengths[tid];

#pragma unroll 4
    for (int rl = 0; rl < 32; ++rl) {
        const int grow = (rl >> 3) * Hn + u0 + (rl & 7);
        const float* wr = Whh + (size_t)grow * Hn;
        Wst[(size_t)tid * 36 + rl]         = wr[tid];
        Wst[(size_t)(tid + 256) * 36 + rl] = wr[tid + 256];
    }
    __syncthreads();

    const int ry = tid >> 5, bx = tid & 31;

    for (int s = 0; s < Tn; ++s) {
        ull acc[4][2];
#pragma unroll
        for (int i = 0; i < 4; ++i) {
            const int rl = 4 * ry + i;
            const int grow = (rl >> 3) * Hn + u0 + (rl & 7);
#pragma unroll
            for (int j = 0; j < 2; ++j) {
                float v[2];
#pragma unroll
                for (int e = 0; e < 2; ++e) {
                    const int b = 2 * bx + 64 * j + e;
                    const int L = slen[b];
                    const bool ok = (s < L);
                    const int t = ok ? (dir ? (L - 1 - s) : s) : 0;
                    v[e] = ok ? __ldg(gx + (size_t)(b * Tn + t) * 2048 + grow) : 0.0f;
                }
                acc[i][j] = pack2(v[0], v[1]);
            }
        }

        if (s > 0) {
            if (tid == 0) {
                const unsigned tgt = 64u * (unsigned)s;
                unsigned v;
                for (;;) {
                    asm volatile("ld.acquire.gpu.u32 %0, [%1];" : "=r"(v) : "l"(ctr));
                    if (v >= tgt) break;
                    __nanosleep(64);
                }
            }
            __syncthreads();

            const float* hp = &g_h[dir][(s - 1) & 1][0];
            for (int kc = 0; kc < 16; ++kc) {
                const float4* src = (const float4*)(hp + kc * 32 * 128);
                float4 hv[4];
#pragma unroll
                for (int i = 0; i < 4; ++i) hv[i] = __ldcg(src + tid + 256 * i);
                __syncthreads();
                float4* d4 = (float4*)Hs;
#pragma unroll
                for (int i = 0; i < 4; ++i) d4[tid + 256 * i] = hv[i];
                __syncthreads();

#pragma unroll 4
                for (int k = 0; k < 32; ++k) {
                    const float4 wv = *(const float4*)&Wst[(size_t)(kc * 32 + k) * 36 + 4 * ry];
                    const ull h0 = *(const ull*)&Hs[k * 128 + 2 * bx];
                    const ull h1 = *(const ull*)&Hs[k * 128 + 2 * bx + 64];
                    const ull w0 = dup2(wv.x), w1 = dup2(wv.y);
                    const ull w2 = dup2(wv.z), w3 = dup2(wv.w);
                    acc[0][0] = ffma2(w0, h0, acc[0][0]);
                    acc[0][1] = ffma2(w0, h1, acc[0][1]);
                    acc[1][0] = ffma2(w1, h0, acc[1][0]);
                    acc[1][1] = ffma2(w1, h1, acc[1][1]);
                    acc[2][0] = ffma2(w2, h0, acc[2][0]);
                    acc[2][1] = ffma2(w2, h1, acc[2][1]);
                    acc[3][0] = ffma2(w3, h0, acc[3][0]);
                    acc[3][1] = ffma2(w3, h1, acc[3][1]);
                }
            }
        }

#pragma unroll
        for (int i = 0; i < 4; ++i) {
            *(ull*)&Gs[(4 * ry + i) * 128 + 2 * bx]      = acc[i][0];
            *(ull*)&Gs[(4 * ry + i) * 128 + 2 * bx + 64] = acc[i][1];
        }
        __syncthreads();

        float* hw = &g_h[dir][s & 1][0];
#pragma unroll
        for (int q = 0; q < 4; ++q) {
            const int cell = tid + 256 * q;
            const int u = cell >> 7, b = cell & 127;
            const int L = slen[b];
            float hval = 0.0f;
            int t = s;
            if (s < L) {
                const float gi = Gs[u * 128 + b];
                const float gf = Gs[(8 + u) * 128 + b];
                const float gg = Gs[(16 + u) * 128 + b];
                const float go = Gs[(24 + u) * 128 + b];
                const float cp = (s == 0) ? 0.0f : cs[cell];
                const float cn = fsig(gf) * cp + fsig(gi) * tanhf(gg);
                cs[cell] = cn;
                hval = fsig(go) * tanhf(cn);
                t = dir ? (L - 1 - s) : s;
            }
            hw[(u0 + u) * 128 + b] = hval;
            out[(size_t)(b * Tn + t) * 1024 + dir * Hn + u0 + u] = hval;
        }

        __syncthreads();
        if (tid == 0) {
            __threadfence();
            atomicAdd(ctr, 1u);
        }
    }
}

// ===========================================================================
extern "C" void kernel_launch(void* const* d_in, const int* in_sizes, int n_in,
                              void* d_out, int out_size)
{
    const int*   x       = (const int*)d_in[0];
    const int*   lengths = (const int*)d_in[1];
    const float* emb     = (const float*)d_in[2];
    const float* Wih_f1  = (const float*)d_in[3];
    const float* Whh_f1  = (const float*)d_in[4];
    const float* b_f1    = (const float*)d_in[5];
    const float* Wih_b1  = (const float*)d_in[6];
    const float* Whh_b1  = (const float*)d_in[7];
    const float* b_b1    = (const float*)d_in[8];
    const float* Wih_f2  = (const float*)d_in[9];
    const float* Whh_f2  = (const float*)d_in[10];
    const float* b_f2    = (const float*)d_in[11];
    const float* Wih_b2  = (const float*)d_in[12];
    const float* Whh_b2  = (const float*)d_in[13];
    const float* b_b2    = (const float*)d_in[14];
    const float* Wcls    = (const float*)d_in[15];
    const float* bcls    = (const float*)d_in[16];
    float* out = (float*)d_out;
    (void)in_sizes; (void)n_in; (void)out_size;

    float *gx, *o1, *o2;
    cudaGetSymbolAddress((void**)&gx, g_gx);
    cudaGetSymbolAddress((void**)&o1, g_out1);
    cudaGetSymbolAddress((void**)&o2, g_out2);
    __nv_bfloat16 *ah, *al, *ebh, *ebl, *wh, *wl;
    cudaGetSymbolAddress((void**)&ah, g_ah);
    cudaGetSymbolAddress((void**)&al, g_al);
    cudaGetSymbolAddress((void**)&ebh, g_ebh);
    cudaGetSymbolAddress((void**)&ebl, g_ebl);
    cudaGetSymbolAddress((void**)&wh, g_wh);
    cudaGetSymbolAddress((void**)&wl, g_wl);
    __nv_bfloat16* wh0 = wh;               __nv_bfloat16* wl0 = wl;
    __nv_bfloat16* wh1 = wh + 2048 * 1024; __nv_bfloat16* wl1 = wl + 2048 * 1024;
    float* gxf = gx;
    float* gxb = gx + (size_t)Mn * 2048;

    const int recSmem = (512 * 36 + 32 * 128 + 32 * 128 + 8 * 128 + 128) * 4;
    cudaFuncSetAttribute(rec_persist, cudaFuncAttributeMaxDynamicSharedMemorySize, recSmem);
    cudaFuncSetAttribute(gemm_mma<true>,  cudaFuncAttributeMaxDynamicSharedMemorySize, 2 * BUF_SZ);
    cudaFuncSetAttribute(gemm_mma<false>, cudaFuncAttributeMaxDynamicSharedMemorySize, 2 * BUF_SZ);

    const dim3 tcg(16, 512);   // n-blocks fast -> A rows shared in L2

    zero_ctr<<<1, 32>>>();

    // ---- one-time splits for layer 1 ----
    split_k<<<12500, 256>>>(emb, ebh, ebl, 50000 * 256 / 4);
    split_k<<<512, 256>>>(Wih_f1, wh0, wl0, 2048 * 256 / 4);
    split_k<<<512, 256>>>(Wih_b1, wh1, wl1, 2048 * 256 / 4);

    // ---- layer 1 (K=256, embedding gather fused) ----
    gemm_mma<true><<<tcg, 512, 2 * BUF_SZ>>>(ebh, ebl, x, wh0, wl0, b_f1, gxf, 256);
    gemm_mma<true><<<tcg, 512, 2 * BUF_SZ>>>(ebh, ebl, x, wh1, wl1, b_b1, gxb, 256);
    rec_persist<<<128, 256, recSmem>>>(gxf, gxb, Whh_f1, Whh_b1, lengths, o1, 0);

    // ---- splits for layer 2 ----
    split_k<<<65536, 256>>>(o1, ah, al, Mn * 1024 / 4);
    split_k<<<2048, 256>>>(Wih_f2, wh0, wl0, 2048 * 1024 / 4);
    split_k<<<2048, 256>>>(Wih_b2, wh1, wl1, 2048 * 1024 / 4);

    // ---- layer 2 (K=1024) ----
    gemm_mma<false><<<tcg, 512, 2 * BUF_SZ>>>(ah, al, nullptr, wh0, wl0, b_f2, gxf, 1024);
    gemm_mma<false><<<tcg, 512, 2 * BUF_SZ>>>(ah, al, nullptr, wh1, wl1, b_b2, gxb, 1024);
    rec_persist<<<128, 256, recSmem>>>(gxf, gxb, Whh_f2, Whh_b2, lengths, o2, 2);

    // ---- classifier ----
    gemm_cls<<<512, 256>>>(o2, Wcls, bcls, out, 64, 1024);
}